// round 4
// baseline (speedup 1.0000x reference)
#include <cuda_runtime.h>
#include <math.h>

// Problem constants
#define BB 16
#define NPIX (288 * 800)        // 230400 pixels per batch per plane
#define NVEC (NPIX / 4)         // 57600 float4 groups per plane per batch
#define BPB 16                  // blocks per batch -> 256 total blocks
#define GB  (BPB * BB)          // 256 blocks: <= 2/SM even on a 128-SM part
#define TPB 256
#define PTH (BPB * TPB)         // 4096 threads per batch
#define KIT 14                  // main groups per thread: 14*4096 = 57344
#define REM (NVEC - KIT * PTH)  // 256 remainder groups
#define NL 4                    // tracked labels 1..4 (label 0 stats dead)
#define NP1 21                  // 16 sums + 4 cnts + wnll
#define DELTA_V 0.5f

// Scratch (device globals; allocation is forbidden)
__device__ float g_p1[BB][BPB][NP1];
__device__ float g_tot[BB][NP1];
__device__ float g_means[BB][NL][4];
__device__ float g_cnts[BB][NL];
__device__ float g_p2[BB][BPB][NL];
__device__ int   g_t1, g_t2;    // phase tickets (reset by finalize each replay)
__device__ int   g_go;          // phase-2 release flag

__device__ __forceinline__ float warp_sum(float v) {
    #pragma unroll
    for (int o = 16; o > 0; o >>= 1) v += __shfl_xor_sync(0xffffffffu, v, o);
    return v;
}

// ---------------------------------------------------------------------------
struct P1Acc {
    float acc[NL][4];
    float cnt[NL];
    float wnll;
};

// Consume one already-loaded group (4 pixels).
__device__ __forceinline__ void p1_consume(const float4& e0v, const float4& e1v,
                                           const float4& e2v, const float4& e3v,
                                           const int4& lv, const float4& g0v,
                                           const float4& g1v, P1Acc& A) {
    const float ed0[4] = {e0v.x, e0v.y, e0v.z, e0v.w};
    const float ed1[4] = {e1v.x, e1v.y, e1v.z, e1v.w};
    const float ed2[4] = {e2v.x, e2v.y, e2v.z, e2v.w};
    const float ed3[4] = {e3v.x, e3v.y, e3v.z, e3v.w};
    const int   lbs[4] = {lv.x, lv.y, lv.z, lv.w};
    const float ga[4]  = {g0v.x, g0v.y, g0v.z, g0v.w};
    const float gb[4]  = {g1v.x, g1v.y, g1v.z, g1v.w};

    #pragma unroll
    for (int p = 0; p < 4; p++) {
        const int L = lbs[p];
        #pragma unroll
        for (int l = 0; l < NL; l++) {
            if (L == l + 1) {
                A.acc[l][0] += ed0[p];
                A.acc[l][1] += ed1[p];
                A.acc[l][2] += ed2[p];
                A.acc[l][3] += ed3[p];
                A.cnt[l]    += 1.f;
            }
        }
        // weighted binary CE:  nll = softplus(tgt ? (a-c) : (c-a))
        const float d  = ga[p] - gb[p];
        const float ax = fabsf(d);
        const int tgt  = (L > 0);
        const float hinge = tgt ? fmaxf(d, 0.f) : fmaxf(-d, 0.f);
        const float sp = hinge + __logf(1.0f + __expf(-ax));
        A.wnll += (tgt ? 1.0f : 0.5f) * sp;
    }
}

// Load+consume a PAIR of groups: all 14 loads issued before any consumption
// (high MLP under the 128-reg budget).
__device__ __forceinline__ void p1_pair(const float* e0, const float* s0,
                                        const int* l0, int i0, int i1, P1Acc& A) {
    float4 a0 = __ldg((const float4*)(e0)          + i0);
    float4 a1 = __ldg((const float4*)(e0 + NPIX)   + i0);
    float4 a2 = __ldg((const float4*)(e0 + 2*NPIX) + i0);
    float4 a3 = __ldg((const float4*)(e0 + 3*NPIX) + i0);
    int4   al = __ldg((const int4*)(l0) + i0);
    float4 ag = __ldcs((const float4*)(s0)         + i0);
    float4 ah = __ldcs((const float4*)(s0 + NPIX)  + i0);
    float4 b0 = __ldg((const float4*)(e0)          + i1);
    float4 b1 = __ldg((const float4*)(e0 + NPIX)   + i1);
    float4 b2 = __ldg((const float4*)(e0 + 2*NPIX) + i1);
    float4 b3 = __ldg((const float4*)(e0 + 3*NPIX) + i1);
    int4   bl = __ldg((const int4*)(l0) + i1);
    float4 bg = __ldcs((const float4*)(s0)         + i1);
    float4 bh = __ldcs((const float4*)(s0 + NPIX)  + i1);
    p1_consume(a0, a1, a2, a3, al, ag, ah, A);
    p1_consume(b0, b1, b2, b3, bl, bg, bh, A);
}

__device__ __forceinline__ void p1_single(const float* e0, const float* s0,
                                          const int* l0, int i, P1Acc& A) {
    float4 a0 = __ldg((const float4*)(e0)          + i);
    float4 a1 = __ldg((const float4*)(e0 + NPIX)   + i);
    float4 a2 = __ldg((const float4*)(e0 + 2*NPIX) + i);
    float4 a3 = __ldg((const float4*)(e0 + 3*NPIX) + i);
    int4   al = __ldg((const int4*)(l0) + i);
    float4 ag = __ldcs((const float4*)(s0)         + i);
    float4 ah = __ldcs((const float4*)(s0 + NPIX)  + i);
    p1_consume(a0, a1, a2, a3, al, ag, ah, A);
}

// ---------------------------------------------------------------------------
__device__ __forceinline__ void p2_consume(const float4& e0v, const float4& e1v,
                                           const float4& e2v, const float4& e3v,
                                           const int4& lv, const float sm[NL][4],
                                           float hs[NL]) {
    const float ed0[4] = {e0v.x, e0v.y, e0v.z, e0v.w};
    const float ed1[4] = {e1v.x, e1v.y, e1v.z, e1v.w};
    const float ed2[4] = {e2v.x, e2v.y, e2v.z, e2v.w};
    const float ed3[4] = {e3v.x, e3v.y, e3v.z, e3v.w};
    const int   lbs[4] = {lv.x, lv.y, lv.z, lv.w};

    #pragma unroll
    for (int p = 0; p < 4; p++) {
        const int L = lbs[p];
        if (L > 0) {
            const int li = L - 1;
            const float d0 = ed0[p] - sm[li][0];
            const float d1 = ed1[p] - sm[li][1];
            const float d2 = ed2[p] - sm[li][2];
            const float d3 = ed3[p] - sm[li][3];
            const float sq = d0*d0 + d1*d1 + d2*d2 + d3*d3;
            const float dist = sqrtf(sq);
            const float tt = fmaxf(dist - DELTA_V, 0.0f);
            const float hv = tt * tt;
            #pragma unroll
            for (int l = 0; l < NL; l++)
                if (li == l) hs[l] += hv;
        }
    }
}

__device__ __forceinline__ void p2_pair(const float* e0, const int* l0,
                                        int i0, int i1,
                                        const float sm[NL][4], float hs[NL]) {
    float4 a0 = __ldg((const float4*)(e0)          + i0);
    float4 a1 = __ldg((const float4*)(e0 + NPIX)   + i0);
    float4 a2 = __ldg((const float4*)(e0 + 2*NPIX) + i0);
    float4 a3 = __ldg((const float4*)(e0 + 3*NPIX) + i0);
    int4   al = __ldg((const int4*)(l0) + i0);
    float4 b0 = __ldg((const float4*)(e0)          + i1);
    float4 b1 = __ldg((const float4*)(e0 + NPIX)   + i1);
    float4 b2 = __ldg((const float4*)(e0 + 2*NPIX) + i1);
    float4 b3 = __ldg((const float4*)(e0 + 3*NPIX) + i1);
    int4   bl = __ldg((const int4*)(l0) + i1);
    p2_consume(a0, a1, a2, a3, al, sm, hs);
    p2_consume(b0, b1, b2, b3, bl, sm, hs);
}

__device__ __forceinline__ void p2_single(const float* e0, const int* l0, int i,
                                          const float sm[NL][4], float hs[NL]) {
    float4 a0 = __ldg((const float4*)(e0)          + i);
    float4 a1 = __ldg((const float4*)(e0 + NPIX)   + i);
    float4 a2 = __ldg((const float4*)(e0 + 2*NPIX) + i);
    float4 a3 = __ldg((const float4*)(e0 + 3*NPIX) + i);
    int4   al = __ldg((const int4*)(l0) + i);
    p2_consume(a0, a1, a2, a3, al, sm, hs);
}

// ---------------------------------------------------------------------------
// One persistent kernel: phase1 -> ticket barrier + means reduce -> phase2
// -> finalize.  grid = (16, 16) = 256 blocks, 2/SM guaranteed (deadlock-safe).
__global__ void __launch_bounds__(TPB, 2)
fused_kernel(const float* __restrict__ emb,
             const float* __restrict__ seg2,
             const int*   __restrict__ lab,
             float* __restrict__ out) {
    const int b   = blockIdx.y;
    const int blk = blockIdx.x;
    const int tid = threadIdx.x;
    const float* e0 = emb  + (size_t)b * 4 * NPIX;
    const float* s0 = seg2 + (size_t)b * 2 * NPIX;
    const int*   l0 = lab  + (size_t)b * NPIX;
    const int base = blk * TPB + tid;          // [0, 4096)

    // ---------------- Phase 1 ----------------
    P1Acc A;
    #pragma unroll
    for (int l = 0; l < NL; l++) {
        A.cnt[l] = 0.f;
        #pragma unroll
        for (int d = 0; d < 4; d++) A.acc[l][d] = 0.f;
    }
    A.wnll = 0.f;

    #pragma unroll
    for (int kp = 0; kp < KIT / 2; kp++)
        p1_pair(e0, s0, l0, base + (2*kp) * PTH, base + (2*kp+1) * PTH, A);
    if (base < REM)
        p1_single(e0, s0, l0, KIT * PTH + base, A);

    // block reduce 21 values -> per-block partial
    {
        __shared__ float sh[TPB / 32][NP1];
        const int wid = tid >> 5, lane = tid & 31;
        float vals[NP1];
        #pragma unroll
        for (int l = 0; l < NL; l++) {
            #pragma unroll
            for (int d = 0; d < 4; d++) vals[l * 4 + d] = A.acc[l][d];
            vals[16 + l] = A.cnt[l];
        }
        vals[20] = A.wnll;
        #pragma unroll
        for (int j = 0; j < NP1; j++) {
            float r = warp_sum(vals[j]);
            if (lane == 0) sh[wid][j] = r;
        }
        __syncthreads();
        if (tid < NP1) {
            float s = 0.f;
            #pragma unroll
            for (int w = 0; w < TPB / 32; w++) s += sh[w][tid];
            g_p1[b][blk][tid] = s;
        }
    }

    // ---------------- Barrier + means reduce ----------------
    __shared__ int sh_last;
    __threadfence();
    __syncthreads();
    if (tid == 0) sh_last = (atomicAdd(&g_t1, 1) == GB - 1);
    __syncthreads();

    if (sh_last) {
        // totals: 16 batches x 21 columns = 336 entries, 16 partials each
        for (int c = tid; c < BB * NP1; c += TPB) {
            const int bb = c / NP1, col = c % NP1;
            float s = 0.f;
            #pragma unroll
            for (int r = 0; r < BPB; r++) s += g_p1[bb][r][col];
            g_tot[bb][col] = s;
        }
        __syncthreads();
        {   // means + counts: 16 batches x 16 entries = 256 threads
            const int bb = tid >> 4, j = tid & 15;
            const float c = g_tot[bb][16 + (j >> 2)];
            g_means[bb][j >> 2][j & 3] = g_tot[bb][j] / fmaxf(c, 1.0f);
            if (j < NL) g_cnts[bb][j] = g_tot[bb][16 + j];
        }
        __threadfence();
        __syncthreads();
        if (tid == 0) *(volatile int*)&g_go = 1;
    } else {
        if (tid == 0) {
            while (*(volatile int*)&g_go == 0) __nanosleep(64);
        }
        __syncthreads();
        __threadfence();
    }

    // ---------------- Phase 2 ----------------
    __shared__ float sm[NL][4];
    if (tid < NL * 4) sm[tid >> 2][tid & 3] = g_means[b][tid >> 2][tid & 3];
    __syncthreads();

    float hs[NL] = {0.f, 0.f, 0.f, 0.f};
    #pragma unroll
    for (int kp = 0; kp < KIT / 2; kp++)
        p2_pair(e0, l0, base + (2*kp) * PTH, base + (2*kp+1) * PTH, sm, hs);
    if (base < REM)
        p2_single(e0, l0, KIT * PTH + base, sm, hs);

    {
        __shared__ float shh[TPB / 32][NL];
        const int wid = tid >> 5, lane = tid & 31;
        #pragma unroll
        for (int l = 0; l < NL; l++) {
            float r = warp_sum(hs[l]);
            if (lane == 0) shh[wid][l] = r;
        }
        __syncthreads();
        if (tid < NL) {
            float s = 0.f;
            #pragma unroll
            for (int w = 0; w < TPB / 32; w++) s += shh[w][tid];
            g_p2[b][blk][tid] = s;
        }
    }

    // ---------------- Finalize (last phase-2 block) ----------------
    __shared__ int sh_last2;
    __threadfence();
    __syncthreads();
    if (tid == 0) sh_last2 = (atomicAdd(&g_t2, 1) == GB - 1);
    __syncthreads();
    if (!sh_last2) return;

    __shared__ float fh[BB * NL];
    if (tid < BB * NL) {
        const int bb = tid >> 2, l = tid & 3;
        float s = 0.f;
        #pragma unroll
        for (int r = 0; r < BPB; r++) s += g_p2[bb][r][l];
        fh[tid] = s;
    }
    __syncthreads();
    if (tid == 0) {
        float var_tot = 0.f, wnll = 0.f, cfg = 0.f;
        #pragma unroll
        for (int bb = 0; bb < BB; bb++) {
            float nlanes = 0.f, sv = 0.f;
            #pragma unroll
            for (int l = 0; l < NL; l++) {
                const float c = g_cnts[bb][l];
                if (c > 0.f) {
                    nlanes += 1.f;
                    sv += fh[bb * NL + l] / c;
                }
                cfg += c;
            }
            var_tot += sv / fmaxf(nlanes, 1.f);
            wnll += g_tot[bb][20];
        }
        const float wsum = 0.5f * (float)(BB * NPIX) + 0.5f * cfg;
        // dist_loss == 0 identically (delta_d added to all pair distances);
        // reg_loss == 0.  loss = seg_ce + var.
        out[0] = wnll / wsum + var_tot / (float)BB;
        // reset persistent state for the next graph replay
        g_t1 = 0;
        g_t2 = 0;
        __threadfence();
        *(volatile int*)&g_go = 0;
    }
}

// ---------------------------------------------------------------------------
extern "C" void kernel_launch(void* const* d_in, const int* in_sizes, int n_in,
                              void* d_out, int out_size) {
    const float* emb  = (const float*)d_in[0];  // [16,4,288,800] f32
    const float* bseg = (const float*)d_in[1];  // [16,2,288,800] f32
    const int*   lab  = (const int*)  d_in[2];  // [16,288,800]   i32
    float* out = (float*)d_out;
    (void)in_sizes; (void)n_in; (void)out_size;

    dim3 grid(BPB, BB);
    fused_kernel<<<grid, TPB>>>(emb, bseg, lab, out);
}

// round 5
// speedup vs baseline: 1.4767x; 1.4767x over previous
#include <cuda_runtime.h>
#include <math.h>

// Problem constants
#define BB 16
#define NPIX (288 * 800)        // 230400 pixels per batch per plane
#define NVEC (NPIX / 4)         // 57600 float4 groups per plane per batch
#define BPB 45                  // blocks per batch -> 720 total (<=740 resident @5/SM)
#define GB  (BPB * BB)          // 720
#define TPB 256
#define KIT 5                   // exactly 5 groups/thread: 45*256*5 = 57600
#define NL 4                    // tracked labels 1..4 (label 0 stats dead)
#define NP1 20                  // 16 sums + 4 counts
#define NP2 5                   // 4 hinge + wnll
#define DELTA_V 0.5f

// Scratch (device globals; allocation is forbidden)
__device__ float g_p1[BB][BPB][NP1];   // pass1 per-block partials
__device__ float g_p2[BB][BPB][NP2];   // pass2 per-block partials
__device__ float g_cnts[BB][NL];       // written by pass2 blk==0 of each batch
__device__ int   g_t2;                 // pass2 finalize ticket (reset each replay)

__device__ __forceinline__ float warp_sum(float v) {
    #pragma unroll
    for (int o = 16; o > 0; o >>= 1) v += __shfl_xor_sync(0xffffffffu, v, o);
    return v;
}

// ---------------------------------------------------------------------------
// Pass 1: per-(b,label) embedding sums + counts only.
// grid=(45,16), block=256, <=50 regs (5 blocks/SM).
__global__ void __launch_bounds__(TPB, 5)
pass1_kernel(const float* __restrict__ emb,
             const int*   __restrict__ lab) {
    const int b   = blockIdx.y;
    const int blk = blockIdx.x;
    const int tid = threadIdx.x;
    const float* e0 = emb + (size_t)b * 4 * NPIX;
    const int*   l0 = lab + (size_t)b * NPIX;
    const int base = blk * (TPB * KIT) + tid;

    float acc[NL][4];
    float cnt[NL];
    #pragma unroll
    for (int l = 0; l < NL; l++) {
        cnt[l] = 0.f;
        #pragma unroll
        for (int d = 0; d < 4; d++) acc[l][d] = 0.f;
    }

    #pragma unroll
    for (int k = 0; k < KIT; k++) {
        const int i = base + k * TPB;
        float4 e0v = __ldg((const float4*)(e0)          + i);
        float4 e1v = __ldg((const float4*)(e0 + NPIX)   + i);
        float4 e2v = __ldg((const float4*)(e0 + 2*NPIX) + i);
        float4 e3v = __ldg((const float4*)(e0 + 3*NPIX) + i);
        int4   lv  = __ldg((const int4*)(l0) + i);

        const float ed0[4] = {e0v.x, e0v.y, e0v.z, e0v.w};
        const float ed1[4] = {e1v.x, e1v.y, e1v.z, e1v.w};
        const float ed2[4] = {e2v.x, e2v.y, e2v.z, e2v.w};
        const float ed3[4] = {e3v.x, e3v.y, e3v.z, e3v.w};
        const int   lbs[4] = {lv.x, lv.y, lv.z, lv.w};

        #pragma unroll
        for (int p = 0; p < 4; p++) {
            const int L = lbs[p];
            #pragma unroll
            for (int l = 0; l < NL; l++) {
                if (L == l + 1) {
                    acc[l][0] += ed0[p];
                    acc[l][1] += ed1[p];
                    acc[l][2] += ed2[p];
                    acc[l][3] += ed3[p];
                    cnt[l]    += 1.f;
                }
            }
        }
    }

    // block reduce 20 values -> per-block partial
    __shared__ float sh[TPB / 32][NP1];
    const int wid = tid >> 5, lane = tid & 31;
    float vals[NP1];
    #pragma unroll
    for (int l = 0; l < NL; l++) {
        #pragma unroll
        for (int d = 0; d < 4; d++) vals[l * 4 + d] = acc[l][d];
        vals[16 + l] = cnt[l];
    }
    #pragma unroll
    for (int j = 0; j < NP1; j++) {
        float r = warp_sum(vals[j]);
        if (lane == 0) sh[wid][j] = r;
    }
    __syncthreads();
    if (tid < NP1) {
        float s = 0.f;
        #pragma unroll
        for (int w = 0; w < TPB / 32; w++) s += sh[w][tid];
        g_p1[b][blk][tid] = s;
    }
}

// ---------------------------------------------------------------------------
// Pass 2: each block (a) redundantly reduces its batch's pass1 partials to
// means (deterministic fixed order), (b) computes hinge + weighted CE over
// its slice, (c) last block finalizes the scalar loss.
__global__ void __launch_bounds__(TPB, 5)
pass2_kernel(const float* __restrict__ emb,
             const float* __restrict__ seg2,
             const int*   __restrict__ lab,
             float* __restrict__ out) {
    const int b   = blockIdx.y;
    const int blk = blockIdx.x;
    const int tid = threadIdx.x;
    const float* e0 = emb  + (size_t)b * 4 * NPIX;
    const float* s0 = seg2 + (size_t)b * 2 * NPIX;
    const int*   l0 = lab  + (size_t)b * NPIX;
    const int base = blk * (TPB * KIT) + tid;

    // ---- means from pass1 partials (every block, deterministic) ----
    __shared__ float red[NP1][8];
    __shared__ float tot[NP1];
    __shared__ float sm[NL][4];
    if (tid < NP1 * 8) {
        const int col = tid >> 3, sub = tid & 7;
        float s = 0.f;
        for (int p = sub; p < BPB; p += 8) s += g_p1[b][p][col];
        red[col][sub] = s;
    }
    __syncthreads();
    if (tid < NP1) {
        float s = 0.f;
        #pragma unroll
        for (int u = 0; u < 8; u++) s += red[tid][u];
        tot[tid] = s;
    }
    __syncthreads();
    if (tid < 16) {
        sm[tid >> 2][tid & 3] = tot[tid] / fmaxf(tot[16 + (tid >> 2)], 1.0f);
        if (blk == 0 && tid < NL) g_cnts[b][tid] = tot[16 + tid];
    }
    __syncthreads();

    // ---- main loop: hinge + CE ----
    float hs[NL] = {0.f, 0.f, 0.f, 0.f};
    float wnll = 0.f;

    #pragma unroll
    for (int k = 0; k < KIT; k++) {
        const int i = base + k * TPB;
        float4 e0v = __ldg((const float4*)(e0)          + i);
        float4 e1v = __ldg((const float4*)(e0 + NPIX)   + i);
        float4 e2v = __ldg((const float4*)(e0 + 2*NPIX) + i);
        float4 e3v = __ldg((const float4*)(e0 + 3*NPIX) + i);
        int4   lv  = __ldg((const int4*)(l0) + i);
        float4 g0v = __ldg((const float4*)(s0)          + i);
        float4 g1v = __ldg((const float4*)(s0 + NPIX)   + i);

        const float ed0[4] = {e0v.x, e0v.y, e0v.z, e0v.w};
        const float ed1[4] = {e1v.x, e1v.y, e1v.z, e1v.w};
        const float ed2[4] = {e2v.x, e2v.y, e2v.z, e2v.w};
        const float ed3[4] = {e3v.x, e3v.y, e3v.z, e3v.w};
        const int   lbs[4] = {lv.x, lv.y, lv.z, lv.w};
        const float ga[4]  = {g0v.x, g0v.y, g0v.z, g0v.w};
        const float gb[4]  = {g1v.x, g1v.y, g1v.z, g1v.w};

        #pragma unroll
        for (int p = 0; p < 4; p++) {
            const int L = lbs[p];
            if (L > 0) {
                const int li = L - 1;          // dynamic index into shared
                const float d0 = ed0[p] - sm[li][0];
                const float d1 = ed1[p] - sm[li][1];
                const float d2 = ed2[p] - sm[li][2];
                const float d3 = ed3[p] - sm[li][3];
                const float sq = d0*d0 + d1*d1 + d2*d2 + d3*d3;
                const float dist = sqrtf(sq);
                const float tt = fmaxf(dist - DELTA_V, 0.0f);
                const float hv = tt * tt;
                #pragma unroll
                for (int l = 0; l < NL; l++)
                    if (li == l) hs[l] += hv;
            }
            // weighted binary CE: nll = softplus(tgt ? (a-c) : (c-a))
            const float d  = ga[p] - gb[p];
            const float ax = fabsf(d);
            const int tgt  = (L > 0);
            const float hinge = tgt ? fmaxf(d, 0.f) : fmaxf(-d, 0.f);
            const float sp = hinge + __logf(1.0f + __expf(-ax));
            wnll += (tgt ? 1.0f : 0.5f) * sp;
        }
    }

    // block reduce 5 values -> per-block partial
    {
        __shared__ float shh[TPB / 32][NP2];
        const int wid = tid >> 5, lane = tid & 31;
        float vals[NP2] = {hs[0], hs[1], hs[2], hs[3], wnll};
        #pragma unroll
        for (int j = 0; j < NP2; j++) {
            float r = warp_sum(vals[j]);
            if (lane == 0) shh[wid][j] = r;
        }
        __syncthreads();
        if (tid < NP2) {
            float s = 0.f;
            #pragma unroll
            for (int w = 0; w < TPB / 32; w++) s += shh[w][tid];
            g_p2[b][blk][tid] = s;
        }
    }

    // ---- finalize in the last block (ticket; no waiting => no deadlock) ----
    __shared__ int sh_last;
    __threadfence();
    __syncthreads();
    if (tid == 0) sh_last = (atomicAdd(&g_t2, 1) == GB - 1);
    __syncthreads();
    if (!sh_last) return;

    __shared__ float fin[BB * NP2];       // 80 reduced values
    if (tid < BB * NP2) {
        const int bb = tid / NP2, j = tid % NP2;
        float s = 0.f;
        #pragma unroll
        for (int p = 0; p < BPB; p++) s += g_p2[bb][p][j];
        fin[tid] = s;
    }
    __syncthreads();
    if (tid == 0) {
        float var_tot = 0.f, wn = 0.f, cfg = 0.f;
        #pragma unroll
        for (int bb = 0; bb < BB; bb++) {
            float nlanes = 0.f, sv = 0.f;
            #pragma unroll
            for (int l = 0; l < NL; l++) {
                const float c = g_cnts[bb][l];
                if (c > 0.f) {
                    nlanes += 1.f;
                    sv += fin[bb * NP2 + l] / c;
                }
                cfg += c;
            }
            var_tot += sv / fmaxf(nlanes, 1.f);
            wn += fin[bb * NP2 + 4];
        }
        const float wsum = 0.5f * (float)(BB * NPIX) + 0.5f * cfg;
        // dist_loss == 0 identically (delta_d added to all pair distances);
        // reg_loss == 0.  loss = seg_ce + var.
        out[0] = wn / wsum + var_tot / (float)BB;
        g_t2 = 0;   // reset for the next graph replay
    }
}

// ---------------------------------------------------------------------------
extern "C" void kernel_launch(void* const* d_in, const int* in_sizes, int n_in,
                              void* d_out, int out_size) {
    const float* emb  = (const float*)d_in[0];  // [16,4,288,800] f32
    const float* bseg = (const float*)d_in[1];  // [16,2,288,800] f32
    const int*   lab  = (const int*)  d_in[2];  // [16,288,800]   i32
    float* out = (float*)d_out;
    (void)in_sizes; (void)n_in; (void)out_size;

    dim3 grid(BPB, BB);
    pass1_kernel<<<grid, TPB>>>(emb, lab);
    pass2_kernel<<<grid, TPB>>>(emb, bseg, lab, out);
}